// round 4
// baseline (speedup 1.0000x reference)
#include <cuda_runtime.h>
#include <math.h>

// ---------------- problem constants ----------------
constexpr int D_M    = 1024;
constexpr int D_S    = 64;
constexpr int H_D    = 32;
constexpr int N_H    = 32;
constexpr int C_S    = 256;
constexpr int N_B    = 2;
constexpr int L_L    = 4096;
constexpr int N_C    = L_L / C_S;            // 16 chunks per batch
constexpr int D_PROJ = D_M + 2 * D_S + N_H;  // 1184
constexpr int M_TOT  = N_B * L_L;            // 8192
constexpr int N_CHNK = N_B * N_C;            // 32 total chunks

// ---------------- scratch (static device globals; no runtime alloc) ----------------
__device__ float g_xbcdt [M_TOT * D_PROJ];                  // 38.8 MB
__device__ float g_Acum  [N_CHNK * N_H * C_S];              // 1 MB
__device__ float g_dtv   [N_CHNK * N_H * C_S];              // 1 MB
__device__ float g_CB    [(size_t)N_CHNK * C_S * C_S];      // 8.4 MB
__device__ float g_states[(size_t)N_CHNK * N_H * H_D * D_S];// 8.4 MB
__device__ float g_prev  [(size_t)N_CHNK * N_H * H_D * D_S];// 8.4 MB
__device__ float g_y     [(size_t)M_TOT * D_M];             // 33.5 MB

// ---------------- fast exp for x <= 0 (FMA pipe, avoids MUFU throughput wall) ----
__device__ __forceinline__ float fexp(float x) {
    x = fmaxf(x, -80.0f);                       // exp(-80) ~ 1.8e-35, negligible
    float y = x * 1.4426950408889634f;          // log2(e)
    float z = y + 12582912.0f;                  // 1.5*2^23: round-to-nearest int
    float n = z - 12582912.0f;
    float f = y - n;                            // f in [-0.5, 0.5]
    int   ei = __float_as_int(z) - 0x4B400000;  // integer n
    float s  = __int_as_float((ei + 127) << 23);// 2^n (n >= -116 after clamp)
    float t = f * 0.6931471805599453f;
    float p = 1.0f + t*(1.0f + t*(0.5f + t*(0.16666667f + t*(0.041666668f + t*0.008333334f))));
    return p * s;
}

// ---------------- GEMM: C[M,N] = A[M,K] * W[N,K]^T (both K-contiguous) ------------
template<bool GUARDN>
__global__ void __launch_bounds__(256, 2)
gemm_nt(const float* __restrict__ A, const float* __restrict__ W,
        float* __restrict__ C, int M, int N, int K)
{
    constexpr int BK = 16;
    __shared__ float As[2][BK][128];
    __shared__ float Bs[2][BK][128];

    const int tid   = threadIdx.x;
    const int m0    = blockIdx.y * 128;
    const int n0    = blockIdx.x * 128;
    const int ldRow = tid >> 2;            // 0..63
    const int ldCol = (tid & 3) << 2;      // 0,4,8,12
    const int tr    = (tid >> 4) << 3;     // 0..120
    const int tc    = (tid & 15) << 3;     // 0..120

    float4 pa0, pa1, pb0, pb1;
    const float4 f4z = make_float4(0.f, 0.f, 0.f, 0.f);

    // ---- load tile 0 into regs
    {
        const float* Ap = A + (size_t)(m0 + ldRow) * K + ldCol;
        pa0 = *(const float4*)Ap;
        pa1 = *(const float4*)(Ap + (size_t)64 * K);
        pb0 = (!GUARDN || (n0 + ldRow)      < N) ? *(const float4*)(W + (size_t)(n0 + ldRow)      * K + ldCol) : f4z;
        pb1 = (!GUARDN || (n0 + ldRow + 64) < N) ? *(const float4*)(W + (size_t)(n0 + ldRow + 64) * K + ldCol) : f4z;
    }
#define STORE_TILE(buf)                                                        \
    do {                                                                       \
        As[buf][ldCol+0][ldRow]    = pa0.x; As[buf][ldCol+1][ldRow]    = pa0.y;\
        As[buf][ldCol+2][ldRow]    = pa0.z; As[buf][ldCol+3][ldRow]    = pa0.w;\
        As[buf][ldCol+0][ldRow+64] = pa1.x; As[buf][ldCol+1][ldRow+64] = pa1.y;\
        As[buf][ldCol+2][ldRow+64] = pa1.z; As[buf][ldCol+3][ldRow+64] = pa1.w;\
        Bs[buf][ldCol+0][ldRow]    = pb0.x; Bs[buf][ldCol+1][ldRow]    = pb0.y;\
        Bs[buf][ldCol+2][ldRow]    = pb0.z; Bs[buf][ldCol+3][ldRow]    = pb0.w;\
        Bs[buf][ldCol+0][ldRow+64] = pb1.x; Bs[buf][ldCol+1][ldRow+64] = pb1.y;\
        Bs[buf][ldCol+2][ldRow+64] = pb1.z; Bs[buf][ldCol+3][ldRow+64] = pb1.w;\
    } while (0)

    STORE_TILE(0);
    __syncthreads();

    float acc[8][8];
#pragma unroll
    for (int i = 0; i < 8; ++i)
#pragma unroll
        for (int j = 0; j < 8; ++j) acc[i][j] = 0.f;

    const int T = K / BK;
    for (int kt = 0; kt < T; ++kt) {
        const int cur = kt & 1;
        if (kt + 1 < T) {
            const int k0 = (kt + 1) * BK;
            const float* Ap = A + (size_t)(m0 + ldRow) * K + k0 + ldCol;
            pa0 = *(const float4*)Ap;
            pa1 = *(const float4*)(Ap + (size_t)64 * K);
            pb0 = (!GUARDN || (n0 + ldRow)      < N) ? *(const float4*)(W + (size_t)(n0 + ldRow)      * K + k0 + ldCol) : f4z;
            pb1 = (!GUARDN || (n0 + ldRow + 64) < N) ? *(const float4*)(W + (size_t)(n0 + ldRow + 64) * K + k0 + ldCol) : f4z;
        }
#pragma unroll
        for (int k = 0; k < BK; ++k) {
            float4 a0 = *(const float4*)&As[cur][k][tr];
            float4 a1 = *(const float4*)&As[cur][k][tr + 4];
            float4 b0 = *(const float4*)&Bs[cur][k][tc];
            float4 b1 = *(const float4*)&Bs[cur][k][tc + 4];
            float av[8] = {a0.x, a0.y, a0.z, a0.w, a1.x, a1.y, a1.z, a1.w};
            float bv[8] = {b0.x, b0.y, b0.z, b0.w, b1.x, b1.y, b1.z, b1.w};
#pragma unroll
            for (int i = 0; i < 8; ++i)
#pragma unroll
                for (int j = 0; j < 8; ++j) acc[i][j] += av[i] * bv[j];
        }
        if (kt + 1 < T) STORE_TILE(cur ^ 1);
        __syncthreads();
    }
#undef STORE_TILE

#pragma unroll
    for (int i = 0; i < 8; ++i) {
        const int gm = m0 + tr + i;
        float* Cp = C + (size_t)gm * N + n0 + tc;
        if (!GUARDN || (n0 + tc) < N) {  // N % 8 == 0 and tc aligned -> whole group valid
            float4 v0 = make_float4(acc[i][0], acc[i][1], acc[i][2], acc[i][3]);
            float4 v1 = make_float4(acc[i][4], acc[i][5], acc[i][6], acc[i][7]);
            *(float4*)Cp       = v0;
            *(float4*)(Cp + 4) = v1;
        }
    }
}

// ---------------- dt = softplus(raw + bias), a = dt*A, per-chunk inclusive cumsum --
__global__ void k_dt_scan(const float* __restrict__ xbcdt,
                          const float* __restrict__ dt_bias,
                          const float* __restrict__ A_log,
                          float* __restrict__ Acum, float* __restrict__ dtv)
{
    const int blk = blockIdx.x;          // bc*N_H + h
    const int h   = blk & (N_H - 1);
    const int bc  = blk >> 5;
    const int i   = threadIdx.x;
    const size_t m = (size_t)bc * C_S + i;

    float z  = xbcdt[m * D_PROJ + (D_M + 2 * D_S) + h] + dt_bias[h];
    float dt = (z > 20.f) ? z : log1pf(__expf(z));
    float a  = dt * (-__expf(A_log[h]));

    __shared__ float ss[C_S];
    ss[i] = a;
    __syncthreads();
#pragma unroll
    for (int off = 1; off < C_S; off <<= 1) {
        float v = (i >= off) ? ss[i - off] : 0.f;
        __syncthreads();
        ss[i] += v;
        __syncthreads();
    }
    Acum[(size_t)blk * C_S + i] = ss[i];
    dtv [(size_t)blk * C_S + i] = dt;
}

// ---------------- per-(b,c,h) chunk states: states[p,n] = sum_j B[j,n]*w[j]*x[j,p] --
__global__ void __launch_bounds__(256)
k_states(const float* __restrict__ xbcdt,
         const float* __restrict__ Acum, const float* __restrict__ dtv,
         float* __restrict__ states)
{
    extern __shared__ float sm[];
    float* sB = sm;                // [256][65]
    float* sx = sm + C_S * 65;     // [256][32], pre-scaled by dt*decay

    const int blk  = blockIdx.x;   // bc*N_H + h
    const int h    = blk & 31;
    const int bc   = blk >> 5;
    const int tid  = threadIdx.x;
    const int lane = tid & 31;
    const int warp = tid >> 5;
    const size_t m0 = (size_t)bc * C_S;
    const float* AcR = Acum + (size_t)blk * C_S;
    const float* dtR = dtv  + (size_t)blk * C_S;
    const float Alast = AcR[C_S - 1];

    for (int j = warp; j < C_S; j += 8) {
        const float* row = xbcdt + (m0 + j) * D_PROJ;
        float w = fexp(Alast - AcR[j]) * dtR[j];
        sB[j * 65 + lane]      = row[D_M + lane];
        sB[j * 65 + lane + 32] = row[D_M + lane + 32];
        sx[j * 32 + lane]      = row[h * H_D + lane] * w;
    }
    __syncthreads();

    const int p  = tid >> 3;
    const int n0 = (tid & 7) << 3;
    float acc[8];
#pragma unroll
    for (int q = 0; q < 8; ++q) acc[q] = 0.f;
    for (int j = 0; j < C_S; ++j) {
        float xv = sx[j * 32 + p];
        const float* bp = &sB[j * 65 + n0];
#pragma unroll
        for (int q = 0; q < 8; ++q) acc[q] += xv * bp[q];
    }
    float* out = states + (size_t)blk * (H_D * D_S) + p * D_S + n0;
#pragma unroll
    for (int q = 0; q < 8; ++q) out[q] = acc[q];
}

// ---------------- per-(b,c) CB[i,j] = sum_n C[i,n]*B[j,n] ------------------------
__global__ void __launch_bounds__(256)
k_cb(const float* __restrict__ xbcdt, float* __restrict__ CB)
{
    extern __shared__ float sm[];
    float* sC = sm;                // [256][65]
    float* sB = sm + C_S * 65;     // [256][65]

    const int bc   = blockIdx.x;
    const int quad = blockIdx.y;   // i-quarter
    const int tid  = threadIdx.x;
    const int lane = tid & 31;
    const int warp = tid >> 5;
    const size_t m0 = (size_t)bc * C_S;

    for (int j = warp; j < C_S; j += 8) {
        const float* row = xbcdt + (m0 + j) * D_PROJ;
        sB[j * 65 + lane]      = row[D_M + lane];
        sB[j * 65 + lane + 32] = row[D_M + lane + 32];
        sC[j * 65 + lane]      = row[D_M + D_S + lane];
        sC[j * 65 + lane + 32] = row[D_M + D_S + lane + 32];
    }
    __syncthreads();

    const int i  = quad * 64 + (tid >> 2);
    const int js = (tid & 3) * 64;
    float* outRow = CB + ((size_t)bc * C_S + i) * C_S;
    for (int j0 = js; j0 < js + 64; j0 += 4) {
        float a0 = 0.f, a1 = 0.f, a2 = 0.f, a3 = 0.f;
#pragma unroll
        for (int k = 0; k < D_S; ++k) {
            float cv = sC[i * 65 + k];
            a0 += cv * sB[(j0 + 0) * 65 + k];
            a1 += cv * sB[(j0 + 1) * 65 + k];
            a2 += cv * sB[(j0 + 2) * 65 + k];
            a3 += cv * sB[(j0 + 3) * 65 + k];
        }
        *(float4*)&outRow[j0] = make_float4(a0, a1, a2, a3);
    }
}

// ---------------- inter-chunk recurrence: prev[c] = carry; carry = carry*dec + st --
__global__ void k_chunkscan(const float* __restrict__ states,
                            const float* __restrict__ Acum,
                            float* __restrict__ prev)
{
    const int blk = blockIdx.x;    // b*N_H + h
    const int h   = blk & 31;
    const int b   = blk >> 5;
    const int e   = threadIdx.x * 8;
    float s[8];
#pragma unroll
    for (int q = 0; q < 8; ++q) s[q] = 0.f;
    for (int c = 0; c < N_C; ++c) {
        const int bc = b * N_C + c;
        const size_t base = ((size_t)bc * N_H + h) * (H_D * D_S) + e;
#pragma unroll
        for (int q = 0; q < 8; ++q) prev[base + q] = s[q];
        float dec = __expf(Acum[((size_t)bc * N_H + h) * C_S + (C_S - 1)]);
#pragma unroll
        for (int q = 0; q < 8; ++q) s[q] = s[q] * dec + states[base + q];
    }
}

// ---------------- per-(b,c,h) output: Y = diag + off + D*x -----------------------
__global__ void __launch_bounds__(256)
k_y(const float* __restrict__ xbcdt,
    const float* __restrict__ Acum, const float* __restrict__ dtv,
    const float* __restrict__ CB, const float* __restrict__ prev,
    const float* __restrict__ Dp, float* __restrict__ Y)
{
    extern __shared__ float sm[];
    float* sCB   = sm;                         // [256][65] (reused for C tile)
    float* sxdt  = sm + C_S * 65;              // [256][32]
    float* sprev = sxdt + C_S * H_D;           // [64][32] transposed [n][p]
    float* sAc   = sprev + H_D * D_S;          // [256]
    float* sdt   = sAc + C_S;                  // [256]

    const int blk  = blockIdx.x;   // bc*N_H + h
    const int h    = blk & 31;
    const int bc   = blk >> 5;
    const int tid  = threadIdx.x;
    const int lane = tid & 31;
    const int warp = tid >> 5;
    const size_t m0 = (size_t)bc * C_S;

    sAc[tid] = Acum[(size_t)blk * C_S + tid];
    sdt[tid] = dtv [(size_t)blk * C_S + tid];
    __syncthreads();

    for (int j = warp; j < C_S; j += 8)
        sxdt[j * 32 + lane] = xbcdt[(m0 + j) * D_PROJ + h * H_D + lane] * sdt[j];
    {   // coalesced read of prev, transposed store [n][p]
        const float* pv = prev + (size_t)blk * (H_D * D_S);
        const int p  = tid >> 3;
        const int n0 = (tid & 7) << 3;
        float rv[8];
#pragma unroll
        for (int q = 0; q < 8; ++q) rv[q] = pv[p * D_S + n0 + q];
#pragma unroll
        for (int q = 0; q < 8; ++q) sprev[(n0 + q) * H_D + p] = rv[q];
    }
    __syncthreads();

    const int i = tid;
    const float Ai = sAc[i];
    float acc[H_D];
#pragma unroll
    for (int p = 0; p < H_D; ++p) acc[p] = 0.f;

    const float* cbBase = CB + (size_t)bc * C_S * C_S;
    for (int t = 0; t < 4; ++t) {
        __syncthreads();
        const int j0 = t << 6;
        for (int e = tid; e < C_S * 64; e += 256) {     // stage CB tile [256][64]
            int ri = e >> 6, jj = e & 63;
            sCB[ri * 65 + jj] = cbBase[(size_t)ri * C_S + j0 + jj];
        }
        __syncthreads();
        int jc = i - j0 + 1;
        if (jc > 64) jc = 64;
        for (int jj = 0; jj < jc; ++jj) {
            const int j = j0 + jj;
            float w = sCB[i * 65 + jj] * fexp(Ai - sAc[j]);
            const float4* xp = (const float4*)&sxdt[j * 32];
#pragma unroll
            for (int q = 0; q < 8; ++q) {
                float4 xv = xp[q];
                acc[4*q+0] += w * xv.x; acc[4*q+1] += w * xv.y;
                acc[4*q+2] += w * xv.z; acc[4*q+3] += w * xv.w;
            }
        }
    }

    // restage C rows into sCB, then Y_off
    __syncthreads();
    for (int e = tid; e < C_S * D_S; e += 256) {
        int ri = e >> 6, n = e & 63;
        sCB[ri * 65 + n] = xbcdt[(m0 + ri) * D_PROJ + D_M + D_S + n];
    }
    __syncthreads();

    const float eAi = fexp(Ai);
    for (int n = 0; n < D_S; ++n) {
        float cv = sCB[i * 65 + n] * eAi;
        const float4* pp = (const float4*)&sprev[n * H_D];
#pragma unroll
        for (int q = 0; q < 8; ++q) {
            float4 pv = pp[q];
            acc[4*q+0] += cv * pv.x; acc[4*q+1] += cv * pv.y;
            acc[4*q+2] += cv * pv.z; acc[4*q+3] += cv * pv.w;
        }
    }

    // skip connection (x = sxdt/dt) and store
    const float dscale = Dp[h] / sdt[i];
    const float4* xr = (const float4*)&sxdt[i * 32];
    float* yout = g_y + (m0 + i) * D_M + h * H_D;
#pragma unroll
    for (int q = 0; q < 8; ++q) {
        float4 xv = xr[q];
        float4 o;
        o.x = acc[4*q+0] + dscale * xv.x;
        o.y = acc[4*q+1] + dscale * xv.y;
        o.z = acc[4*q+2] + dscale * xv.z;
        o.w = acc[4*q+3] + dscale * xv.w;
        ((float4*)yout)[q] = o;
    }
    (void)Y;
}

// ---------------- launch ----------------
extern "C" void kernel_launch(void* const* d_in, const int* in_sizes, int n_in,
                              void* d_out, int out_size)
{
    const float* u       = (const float*)d_in[0];
    const float* W_in    = (const float*)d_in[1];
    const float* dt_bias = (const float*)d_in[2];
    const float* A_log   = (const float*)d_in[3];
    const float* Dp      = (const float*)d_in[4];
    const float* W_out   = (const float*)d_in[5];
    float* out = (float*)d_out;

    float *xbcdt, *Acum, *dtv, *CBp, *statesp, *prevp, *yp;
    cudaGetSymbolAddress((void**)&xbcdt,  g_xbcdt);
    cudaGetSymbolAddress((void**)&Acum,   g_Acum);
    cudaGetSymbolAddress((void**)&dtv,    g_dtv);
    cudaGetSymbolAddress((void**)&CBp,    g_CB);
    cudaGetSymbolAddress((void**)&statesp,g_states);
    cudaGetSymbolAddress((void**)&prevp,  g_prev);
    cudaGetSymbolAddress((void**)&yp,     g_y);

    const int SMEM_STATES = (C_S * 65 + C_S * 32) * 4;                         // 99328
    const int SMEM_CB     = (2 * C_S * 65) * 4;                                // 133120
    const int SMEM_Y      = (C_S * 65 + C_S * 32 + H_D * D_S + 2 * C_S) * 4;   // 109568
    cudaFuncSetAttribute(k_states, cudaFuncAttributeMaxDynamicSharedMemorySize, SMEM_STATES);
    cudaFuncSetAttribute(k_cb,     cudaFuncAttributeMaxDynamicSharedMemorySize, SMEM_CB);
    cudaFuncSetAttribute(k_y,      cudaFuncAttributeMaxDynamicSharedMemorySize, SMEM_Y);

    // 1) in-projection GEMM: xbcdt = u @ W_in^T   (M=8192, N=1184, K=1024)
    {
        dim3 g((D_PROJ + 127) / 128, M_TOT / 128);
        gemm_nt<true><<<g, 256>>>(u, W_in, xbcdt, M_TOT, D_PROJ, D_M);
    }
    // 2) dt + per-chunk cumulative decay
    k_dt_scan<<<N_CHNK * N_H, C_S>>>(xbcdt, dt_bias, A_log, Acum, dtv);
    // 3) chunk end-states
    k_states<<<N_CHNK * N_H, 256, SMEM_STATES>>>(xbcdt, Acum, dtv, statesp);
    // 4) CB = C @ B^T per chunk
    {
        dim3 g(N_CHNK, 4);
        k_cb<<<g, 256, SMEM_CB>>>(xbcdt, CBp);
    }
    // 5) inter-chunk recurrence
    k_chunkscan<<<N_B * N_H, 256>>>(statesp, Acum, prevp);
    // 6) Y = diag + off + skip
    k_y<<<N_CHNK * N_H, 256, SMEM_Y>>>(xbcdt, Acum, dtv, CBp, prevp, Dp, yp);
    // 7) out-projection GEMM: out = y @ W_out^T   (M=8192, N=1024, K=1024)
    {
        dim3 g(D_M / 128, M_TOT / 128);
        gemm_nt<false><<<g, 256>>>(yp, W_out, out, M_TOT, D_M, D_M);
    }
    (void)in_sizes; (void)n_in; (void)out_size;
}

// round 7
// speedup vs baseline: 1.7145x; 1.7145x over previous
#include <cuda_runtime.h>
#include <cuda_bf16.h>
#include <math.h>
#include <cstdint>

// ---------------- problem constants ----------------
constexpr int D_M    = 1024;
constexpr int D_S    = 64;
constexpr int H_D    = 32;
constexpr int N_H    = 32;
constexpr int C_S    = 256;
constexpr int N_B    = 2;
constexpr int L_L    = 4096;
constexpr int N_C    = L_L / C_S;            // 16 chunks per batch
constexpr int D_PROJ = D_M + 2 * D_S + N_H;  // 1184
constexpr int M_TOT  = N_B * L_L;            // 8192
constexpr int N_CHNK = N_B * N_C;            // 32 total chunks

// ---------------- scratch (static device globals; no runtime alloc) ----------------
__device__ float g_xbcdt [M_TOT * D_PROJ];                  // 38.8 MB
__device__ float g_Acum  [N_CHNK * N_H * C_S];
__device__ float g_dtv   [N_CHNK * N_H * C_S];
__device__ float g_CB    [(size_t)N_CHNK * C_S * C_S];      // 8.4 MB
__device__ float g_states[(size_t)N_CHNK * N_H * H_D * D_S];
__device__ float g_prev  [(size_t)N_CHNK * N_H * H_D * D_S];
__device__ __nv_bfloat16 g_uhi [M_TOT * D_M];               // 16.8 MB
__device__ __nv_bfloat16 g_ulo [M_TOT * D_M];
__device__ __nv_bfloat16 g_w1hi[D_PROJ * D_M];
__device__ __nv_bfloat16 g_w1lo[D_PROJ * D_M];
__device__ __nv_bfloat16 g_w2hi[D_M * D_M];
__device__ __nv_bfloat16 g_w2lo[D_M * D_M];
__device__ __nv_bfloat16 g_yhi [M_TOT * D_M];               // 16.8 MB
__device__ __nv_bfloat16 g_ylo [M_TOT * D_M];

// ================= portable (compute_103) asm helpers =================
__device__ __forceinline__ uint32_t smem_u32(const void* p) {
    uint32_t a;
    asm("{ .reg .u64 t; cvta.to.shared.u64 t, %1; cvt.u32.u64 %0, t; }" : "=r"(a) : "l"(p));
    return a;
}
__device__ __forceinline__ void cp_async16(uint32_t dst, const void* src, int srcsize) {
    asm volatile("cp.async.cg.shared.global [%0], [%1], 16, %2;"
                 :: "r"(dst), "l"(src), "r"(srcsize) : "memory");
}
__device__ __forceinline__ void cp_commit() { asm volatile("cp.async.commit_group;" ::: "memory"); }
template<int N>
__device__ __forceinline__ void cp_wait() { asm volatile("cp.async.wait_group %0;" :: "n"(N) : "memory"); }

__device__ __forceinline__ void ldsm4(uint32_t* r, uint32_t addr) {
    asm volatile("ldmatrix.sync.aligned.m8n8.x4.shared.b16 {%0,%1,%2,%3}, [%4];"
                 : "=r"(r[0]), "=r"(r[1]), "=r"(r[2]), "=r"(r[3]) : "r"(addr));
}
__device__ __forceinline__ void mma16816(float* c, const uint32_t* a, const uint32_t* b) {
    asm volatile(
        "mma.sync.aligned.m16n8k16.row.col.f32.bf16.bf16.f32 "
        "{%0,%1,%2,%3}, {%4,%5,%6,%7}, {%8,%9}, {%0,%1,%2,%3};"
        : "+f"(c[0]), "+f"(c[1]), "+f"(c[2]), "+f"(c[3])
        : "r"(a[0]), "r"(a[1]), "r"(a[2]), "r"(a[3]), "r"(b[0]), "r"(b[1]));
}

#define SWZ128(off) ((off) ^ (((off) >> 3) & 0x70))

// ---------------- fast exp for x <= 0 (FMA pipe) ----------------
__device__ __forceinline__ float fexp(float x) {
    x = fmaxf(x, -80.0f);
    float y = x * 1.4426950408889634f;
    float z = y + 12582912.0f;
    float n = z - 12582912.0f;
    float f = y - n;
    int   ei = __float_as_int(z) - 0x4B400000;
    float s  = __int_as_float((ei + 127) << 23);
    float t = f * 0.6931471805599453f;
    float p = 1.0f + t*(1.0f + t*(0.5f + t*(0.16666667f + t*(0.041666668f + t*0.008333334f))));
    return p * s;
}

__device__ __forceinline__ uint32_t bf16pack(__nv_bfloat16 a, __nv_bfloat16 b) {
    return (uint32_t)__bfloat16_as_ushort(a) | ((uint32_t)__bfloat16_as_ushort(b) << 16);
}

// ---------------- fp32 -> (hi,lo) bf16 split ----------------
__global__ void k_split(const float* __restrict__ in, __nv_bfloat16* __restrict__ hi,
                        __nv_bfloat16* __restrict__ lo, int n)
{
    for (int idx = (blockIdx.x * blockDim.x + threadIdx.x) * 4; idx < n;
         idx += gridDim.x * blockDim.x * 4) {
        float4 v = *(const float4*)(in + idx);
        __nv_bfloat16 h0 = __float2bfloat16(v.x), h1 = __float2bfloat16(v.y);
        __nv_bfloat16 h2 = __float2bfloat16(v.z), h3 = __float2bfloat16(v.w);
        __nv_bfloat16 l0 = __float2bfloat16(v.x - __bfloat162float(h0));
        __nv_bfloat16 l1 = __float2bfloat16(v.y - __bfloat162float(h1));
        __nv_bfloat16 l2 = __float2bfloat16(v.z - __bfloat162float(h2));
        __nv_bfloat16 l3 = __float2bfloat16(v.w - __bfloat162float(h3));
        *(uint2*)(hi + idx) = make_uint2(bf16pack(h0, h1), bf16pack(h2, h3));
        *(uint2*)(lo + idx) = make_uint2(bf16pack(l0, l1), bf16pack(l2, l3));
    }
}

// ================= tensor-core GEMM (mma.sync HMMA path) =================
// C[M, Ncols] = A[M,1024] * B[Ncols,1024]^T via 3xBF16 split, fp32 accum.
// 128x128 CTA tile; 8 warps (4 over M x 2 over N), warp tile 32x64.
// K staged 64 bf16 (128B rows, SW128 xor swizzle), cp.async double buffer.
constexpr int GEMM_SMEM = 2 * 4 * 16384;   // 2 stages x 4 operands x 16KB = 128KB

template<bool GUARDN>
__global__ void __launch_bounds__(256)
gemm_tc(const __nv_bfloat16* __restrict__ Ahi, const __nv_bfloat16* __restrict__ Alo,
        const __nv_bfloat16* __restrict__ Bhi, const __nv_bfloat16* __restrict__ Blo,
        float* __restrict__ C, int Nrows)
{
    extern __shared__ char smem[];
    const uint32_t sb = smem_u32(smem);
    const int tid  = threadIdx.x;
    const int lane = tid & 31;
    const int wid  = tid >> 5;
    const int m0   = blockIdx.y * 128;
    const int n0   = blockIdx.x * 128;
    const int wm   = wid & 3;        // warp row: 32 M-rows each
    const int wn   = wid >> 2;       // warp col: 64 N-cols each
    constexpr int K = 1024;
    constexpr int NSTAGE = 16;

    // ---- stage loader: 4 tiles (Ahi,Alo,Bhi,Blo) of 128rows x 64bf16, swizzled
#define LOAD_STAGE(kt, buf)                                                     \
    do {                                                                        \
        const int _k0 = (kt) * 64;                                              \
        const int _bb = (buf) * 65536;                                          \
        _Pragma("unroll")                                                       \
        for (int _i = 0; _i < 16; ++_i) {                                       \
            const int _op  = _i >> 2;                                           \
            const int _c   = ((_i * 256 + tid) & 1023);                         \
            const int _row = _c >> 3, _g = _c & 7;                              \
            const uint32_t _dst = sb + _bb + _op * 16384                        \
                                + SWZ128(_row * 128 + _g * 16);                 \
            if (_op < 2) {                                                      \
                const __nv_bfloat16* _p = (_op == 0 ? Ahi : Alo)                \
                    + (size_t)(m0 + _row) * K + _k0 + _g * 8;                   \
                cp_async16(_dst, _p, 16);                                       \
            } else {                                                            \
                const int _nr = n0 + _row;                                      \
                const bool _ok = (!GUARDN || _nr < Nrows);                      \
                const __nv_bfloat16* _p = (_op == 2 ? Bhi : Blo)                \
                    + (size_t)(_ok ? _nr : 0) * K + _k0 + _g * 8;               \
                cp_async16(_dst, _p, _ok ? 16 : 0);                             \
            }                                                                   \
        }                                                                       \
        cp_commit();                                                            \
    } while (0)

    float acc[2][8][4];
#pragma unroll
    for (int mt = 0; mt < 2; ++mt)
#pragma unroll
        for (int nt = 0; nt < 8; ++nt)
#pragma unroll
            for (int q = 0; q < 4; ++q) acc[mt][nt][q] = 0.f;

    // per-lane ldmatrix address selectors
    const int sub = lane >> 3;
    const int lr  = lane & 7;
    const int a_r = (sub & 1) * 8 + lr;      // A: m8 pairs stacked, then k halves
    const int a_c = (sub >> 1) * 16;
    const int b_r = (sub >> 1) * 8 + lr;     // B: k halves first, then n8 pairs
    const int b_c = (sub & 1) * 16;

    LOAD_STAGE(0, 0);

    for (int kt = 0; kt < NSTAGE; ++kt) {
        const int buf = kt & 1;
        if (kt + 1 < NSTAGE) { LOAD_STAGE(kt + 1, buf ^ 1); cp_wait<1>(); }
        else                 { cp_wait<0>(); }
        __syncthreads();

        const uint32_t tAh = sb + buf * 65536;
        const uint32_t tAl = tAh + 16384;
        const uint32_t tBh = tAh + 32768;
        const uint32_t tBl = tAh + 49152;
#pragma unroll
        for (int ks = 0; ks < 4; ++ks) {
            uint32_t ah[2][4], al[2][4], bh[16], bl[16];
#pragma unroll
            for (int mt = 0; mt < 2; ++mt) {
                const int off = (wm * 32 + mt * 16 + a_r) * 128 + ks * 32 + a_c;
                const uint32_t so = SWZ128(off);
                ldsm4(ah[mt], tAh + so);
                ldsm4(al[mt], tAl + so);
            }
#pragma unroll
            for (int pr = 0; pr < 4; ++pr) {
                const int off = (wn * 64 + pr * 16 + b_r) * 128 + ks * 32 + b_c;
                const uint32_t so = SWZ128(off);
                ldsm4(&bh[pr * 4], tBh + so);
                ldsm4(&bl[pr * 4], tBl + so);
            }
#pragma unroll
            for (int mt = 0; mt < 2; ++mt)
#pragma unroll
                for (int nt = 0; nt < 8; ++nt) {
                    mma16816(acc[mt][nt], ah[mt], &bh[nt * 2]);   // hi*hi
                    mma16816(acc[mt][nt], ah[mt], &bl[nt * 2]);   // hi*lo
                    mma16816(acc[mt][nt], al[mt], &bh[nt * 2]);   // lo*hi
                }
        }
        __syncthreads();
    }
#undef LOAD_STAGE

    // ---- epilogue: m16n8 accum layout -> global
    const int rbase = m0 + wm * 32 + (lane >> 2);
    const int cq    = (lane & 3) * 2;
#pragma unroll
    for (int mt = 0; mt < 2; ++mt) {
#pragma unroll
        for (int nt = 0; nt < 8; ++nt) {
            const int col = n0 + wn * 64 + nt * 8 + cq;
            if (!GUARDN || col < Nrows) {
                float* p = C + (size_t)(rbase + mt * 16) * Nrows + col;
                p[0] = acc[mt][nt][0];
                p[1] = acc[mt][nt][1];
                float* q = p + 8 * (size_t)Nrows;
                q[0] = acc[mt][nt][2];
                q[1] = acc[mt][nt][3];
            }
        }
    }
}

// ---------------- dt = softplus(raw + bias), a = dt*A, per-chunk inclusive cumsum --
__global__ void k_dt_scan(const float* __restrict__ xbcdt,
                          const float* __restrict__ dt_bias,
                          const float* __restrict__ A_log,
                          float* __restrict__ Acum, float* __restrict__ dtv)
{
    const int blk = blockIdx.x;          // bc*N_H + h
    const int h   = blk & (N_H - 1);
    const int bc  = blk >> 5;
    const int i   = threadIdx.x;
    const size_t m = (size_t)bc * C_S + i;

    float z  = xbcdt[m * D_PROJ + (D_M + 2 * D_S) + h] + dt_bias[h];
    float dt = (z > 20.f) ? z : log1pf(__expf(z));
    float a  = dt * (-__expf(A_log[h]));

    __shared__ float ss[C_S];
    ss[i] = a;
    __syncthreads();
#pragma unroll
    for (int off = 1; off < C_S; off <<= 1) {
        float v = (i >= off) ? ss[i - off] : 0.f;
        __syncthreads();
        ss[i] += v;
        __syncthreads();
    }
    Acum[(size_t)blk * C_S + i] = ss[i];
    dtv [(size_t)blk * C_S + i] = dt;
}

// ---------------- per-(b,c,h) chunk states: states[p,n] = sum_j B[j,n]*w[j]*x[j,p] --
__global__ void __launch_bounds__(256)
k_states(const float* __restrict__ xbcdt,
         const float* __restrict__ Acum, const float* __restrict__ dtv,
         float* __restrict__ states)
{
    extern __shared__ float sm[];
    float* sB = sm;                // [256][65]
    float* sx = sm + C_S * 65;     // [256][32], pre-scaled by dt*decay

    const int blk  = blockIdx.x;   // bc*N_H + h
    const int h    = blk & 31;
    const int bc   = blk >> 5;
    const int tid  = threadIdx.x;
    const int lane = tid & 31;
    const int warp = tid >> 5;
    const size_t m0 = (size_t)bc * C_S;
    const float* AcR = Acum + (size_t)blk * C_S;
    const float* dtR = dtv  + (size_t)blk * C_S;
    const float Alast = AcR[C_S - 1];

    for (int j = warp; j < C_S; j += 8) {
        const float* row = xbcdt + (m0 + j) * D_PROJ;
        float w = fexp(Alast - AcR[j]) * dtR[j];
        sB[j * 65 + lane]      = row[D_M + lane];
        sB[j * 65 + lane + 32] = row[D_M + lane + 32];
        sx[j * 32 + lane]      = row[h * H_D + lane] * w;
    }
    __syncthreads();

    const int p  = tid >> 3;
    const int n0 = (tid & 7) << 3;
    float acc[8];
#pragma unroll
    for (int q = 0; q < 8; ++q) acc[q] = 0.f;
    for (int j = 0; j < C_S; ++j) {
        float xv = sx[j * 32 + p];
        const float* bp = &sB[j * 65 + n0];
#pragma unroll
        for (int q = 0; q < 8; ++q) acc[q] += xv * bp[q];
    }
    float* out = states + (size_t)blk * (H_D * D_S) + p * D_S + n0;
#pragma unroll
    for (int q = 0; q < 8; ++q) out[q] = acc[q];
}

// ---------------- per-(b,c) CB[i,j] = sum_n C[i,n]*B[j,n] ------------------------
__global__ void __launch_bounds__(256)
k_cb(const float* __restrict__ xbcdt, float* __restrict__ CB)
{
    extern __shared__ float sm[];
    float* sC = sm;                // [256][65]
    float* sB = sm + C_S * 65;     // [256][65]

    const int bc   = blockIdx.x;
    const int quad = blockIdx.y;   // i-quarter
    const int tid  = threadIdx.x;
    const int lane = tid & 31;
    const int warp = tid >> 5;
    const size_t m0 = (size_t)bc * C_S;

    for (int j = warp; j < C_S; j += 8) {
        const float* row = xbcdt + (m0 + j) * D_PROJ;
        sB[j * 65 + lane]      = row[D_M + lane];
        sB[j * 65 + lane + 32] = row[D_M + lane + 32];
        sC[j * 65 + lane]      = row[D_M + D_S + lane];
        sC[j * 65 + lane + 32] = row[D_M + D_S + lane + 32];
    }
    __syncthreads();

    const int i  = quad * 64 + (tid >> 2);
    const int js = (tid & 3) * 64;
    float* outRow = CB + ((size_t)bc * C_S + i) * C_S;
    for (int j0 = js; j0 < js + 64; j0 += 4) {
        float a0 = 0.f, a1 = 0.f, a2 = 0.f, a3 = 0.f;
#pragma unroll
        for (int k = 0; k < D_S; ++k) {
            float cv = sC[i * 65 + k];
            a0 += cv * sB[(j0 + 0) * 65 + k];
            a1 += cv * sB[(j0 + 1) * 65 + k];
            a2 += cv * sB[(j0 + 2) * 65 + k];
            a3 += cv * sB[(j0 + 3) * 65 + k];
        }
        *(float4*)&outRow[j0] = make_float4(a0, a1, a2, a3);
    }
}

// ---------------- inter-chunk recurrence: prev[c] = carry; carry = carry*dec + st --
__global__ void k_chunkscan(const float* __restrict__ states,
                            const float* __restrict__ Acum,
                            float* __restrict__ prev)
{
    const int blk = blockIdx.x;    // b*N_H + h
    const int h   = blk & 31;
    const int b   = blk >> 5;
    const int e   = threadIdx.x * 8;
    float s[8];
#pragma unroll
    for (int q = 0; q < 8; ++q) s[q] = 0.f;
    for (int c = 0; c < N_C; ++c) {
        const int bc = b * N_C + c;
        const size_t base = ((size_t)bc * N_H + h) * (H_D * D_S) + e;
#pragma unroll
        for (int q = 0; q < 8; ++q) prev[base + q] = s[q];
        float dec = __expf(Acum[((size_t)bc * N_H + h) * C_S + (C_S - 1)]);
#pragma unroll
        for (int q = 0; q < 8; ++q) s[q] = s[q] * dec + states[base + q];
    }
}

// ---------------- per-(b,c,h) output: Y = diag + off + D*x -> split bf16 ---------
__global__ void __launch_bounds__(256)
k_y(const float* __restrict__ xbcdt,
    const float* __restrict__ Acum, const float* __restrict__ dtv,
    const float* __restrict__ CB, const float* __restrict__ prev,
    const float* __restrict__ Dp)
{
    extern __shared__ float sm[];
    float* sCB   = sm;                         // [256][65] (reused for C tile)
    float* sxdt  = sm + C_S * 65;              // [256][32]
    float* sprev = sxdt + C_S * H_D;           // [64][32] transposed [n][p]
    float* sAc   = sprev + H_D * D_S;          // [256]
    float* sdt   = sAc + C_S;                  // [256]

    const int blk  = blockIdx.x;   // bc*N_H + h
    const int h    = blk & 31;
    const int bc   = blk >> 5;
    const int tid  = threadIdx.x;
    const int lane = tid & 31;
    const int warp = tid >> 5;
    const size_t m0 = (size_t)bc * C_S;

    sAc[tid] = Acum[(size_t)blk * C_S + tid];
    sdt[tid] = dtv [(size_t)blk * C_S + tid];
    __syncthreads();

    for (int j = warp; j < C_S; j += 8)
        sxdt[j * 32 + lane] = xbcdt[(m0 + j) * D_PROJ + h * H_D + lane] * sdt[j];
    {   // coalesced read of prev, transposed store [n][p]
        const float* pv = prev + (size_t)blk * (H_D * D_S);
        const int p  = tid >> 3;
        const int n0 = (tid & 7) << 3;
        float rv[8];
#pragma unroll
        for (int q = 0; q < 8; ++q) rv[q] = pv[p * D_S + n0 + q];
#pragma unroll
        for (int q = 0; q < 8; ++q) sprev[(n0 + q) * H_D + p] = rv[q];
    }
    __syncthreads();

    const int i = tid;
    const float Ai = sAc[i];
    float acc[H_D];
#pragma unroll
    for (int p = 0; p < H_D; ++p) acc[p] = 0.f;

    const float* cbBase = CB + (size_t)bc * C_S * C_S;
    for (int t = 0; t < 4; ++t) {
        __syncthreads();
        const int j0 = t << 6;
        for (int e = tid; e < C_S * 64; e += 256) {     // stage CB tile [256][64]
            int ri = e >> 6, jj = e & 63;
            sCB[ri * 65 + jj] = cbBase[(size_t)ri * C_S + j0 + jj];
        }
        __syncthreads();
        int jc = i - j0 + 1;
        if (jc > 64) jc = 64;
        for (int jj = 0; jj < jc; ++jj) {
            const int j = j0 + jj;
            float w = sCB[i * 65 + jj] * fexp(Ai - sAc[j]);
            const float4* xp = (const float4*)&sxdt[j * 32];
#pragma unroll
            for (int q = 0; q < 8; ++q) {
                float4 xv = xp[q];
                acc[4*q+0] += w * xv.x; acc[4*q+1] += w * xv.y;
                acc[4*q+2] += w * xv.z; acc[4*q+3] += w * xv.w;
            }
        }
    }

    // restage C rows into sCB, then Y_off
    __syncthreads();
    for (int e = tid; e < C_S * D_S; e += 256) {
        int ri = e >> 6, n = e & 63;
        sCB[ri * 65 + n] = xbcdt[(m0 + ri) * D_PROJ + D_M + D_S + n];
    }
    __syncthreads();

    const float eAi = fexp(Ai);
    for (int n = 0; n < D_S; ++n) {
        float cv = sCB[i * 65 + n] * eAi;
        const float4* pp = (const float4*)&sprev[n * H_D];
#pragma unroll
        for (int q = 0; q < 8; ++q) {
            float4 pv = pp[q];
            acc[4*q+0] += cv * pv.x; acc[4*q+1] += cv * pv.y;
            acc[4*q+2] += cv * pv.z; acc[4*q+3] += cv * pv.w;
        }
    }

    // skip connection and split-bf16 store (feeds tensor-core GEMM2)
    const float dscale = Dp[h] / sdt[i];
    const float4* xr = (const float4*)&sxdt[i * 32];
    const size_t ybase = (m0 + i) * (size_t)D_M + h * H_D;
    __nv_bfloat16* yh = g_yhi + ybase;
    __nv_bfloat16* yl = g_ylo + ybase;
#pragma unroll
    for (int q = 0; q < 8; ++q) {
        float4 xv = xr[q];
        float o0 = acc[4*q+0] + dscale * xv.x;
        float o1 = acc[4*q+1] + dscale * xv.y;
        float o2 = acc[4*q+2] + dscale * xv.z;
        float o3 = acc[4*q+3] + dscale * xv.w;
        __nv_bfloat16 h0 = __float2bfloat16(o0), h1 = __float2bfloat16(o1);
        __nv_bfloat16 h2 = __float2bfloat16(o2), h3 = __float2bfloat16(o3);
        __nv_bfloat16 l0 = __float2bfloat16(o0 - __bfloat162float(h0));
        __nv_bfloat16 l1 = __float2bfloat16(o1 - __bfloat162float(h1));
        __nv_bfloat16 l2 = __float2bfloat16(o2 - __bfloat162float(h2));
        __nv_bfloat16 l3 = __float2bfloat16(o3 - __bfloat162float(h3));
        *(uint2*)(yh + q * 4) = make_uint2(bf16pack(h0, h1), bf16pack(h2, h3));
        *(uint2*)(yl + q * 4) = make_uint2(bf16pack(l0, l1), bf16pack(l2, l3));
    }
}

// ---------------- launch ----------------
extern "C" void kernel_launch(void* const* d_in, const int* in_sizes, int n_in,
                              void* d_out, int out_size)
{
    const float* u       = (const float*)d_in[0];
    const float* W_in    = (const float*)d_in[1];
    const float* dt_bias = (const float*)d_in[2];
    const float* A_log   = (const float*)d_in[3];
    const float* Dp      = (const float*)d_in[4];
    const float* W_out   = (const float*)d_in[5];
    float* out = (float*)d_out;

    float *xbcdt, *Acum, *dtv, *CBp, *statesp, *prevp;
    __nv_bfloat16 *uhi, *ulo, *w1hi, *w1lo, *w2hi, *w2lo, *yhi, *ylo;
    cudaGetSymbolAddress((void**)&xbcdt,  g_xbcdt);
    cudaGetSymbolAddress((void**)&Acum,   g_Acum);
    cudaGetSymbolAddress((void**)&dtv,    g_dtv);
    cudaGetSymbolAddress((void**)&CBp,    g_CB);
    cudaGetSymbolAddress((void**)&statesp,g_states);
    cudaGetSymbolAddress((void**)&prevp,  g_prev);
    cudaGetSymbolAddress((void**)&uhi,    g_uhi);
    cudaGetSymbolAddress((void**)&ulo,    g_ulo);
    cudaGetSymbolAddress((void**)&w1hi,   g_w1hi);
    cudaGetSymbolAddress((void**)&w1lo,   g_w1lo);
    cudaGetSymbolAddress((void**)&w2hi,   g_w2hi);
    cudaGetSymbolAddress((void**)&w2lo,   g_w2lo);
    cudaGetSymbolAddress((void**)&yhi,    g_yhi);
    cudaGetSymbolAddress((void**)&ylo,    g_ylo);

    const int SMEM_STATES = (C_S * 65 + C_S * 32) * 4;                         // 99328
    const int SMEM_CB     = (2 * C_S * 65) * 4;                                // 133120
    const int SMEM_Y      = (C_S * 65 + C_S * 32 + H_D * D_S + 2 * C_S) * 4;   // 109568
    cudaFuncSetAttribute(k_states, cudaFuncAttributeMaxDynamicSharedMemorySize, SMEM_STATES);
    cudaFuncSetAttribute(k_cb,     cudaFuncAttributeMaxDynamicSharedMemorySize, SMEM_CB);
    cudaFuncSetAttribute(k_y,      cudaFuncAttributeMaxDynamicSharedMemorySize, SMEM_Y);
    cudaFuncSetAttribute(gemm_tc<true>,  cudaFuncAttributeMaxDynamicSharedMemorySize, GEMM_SMEM);
    cudaFuncSetAttribute(gemm_tc<false>, cudaFuncAttributeMaxDynamicSharedMemorySize, GEMM_SMEM);

    // 0) split fp32 inputs into (hi,lo) bf16 pairs
    k_split<<<512, 256>>>(u,     uhi,  ulo,  M_TOT * D_M);
    k_split<<<96,  256>>>(W_in,  w1hi, w1lo, D_PROJ * D_M);
    k_split<<<96,  256>>>(W_out, w2hi, w2lo, D_M * D_M);

    // 1) in-projection GEMM (HMMA): xbcdt = u @ W_in^T  (8192 x 1184 x 1024)
    {
        dim3 g((D_PROJ + 127) / 128, M_TOT / 128);   // 10 x 64
        gemm_tc<true><<<g, 256, GEMM_SMEM>>>(uhi, ulo, w1hi, w1lo, xbcdt, D_PROJ);
    }
    // 2) dt + per-chunk cumulative decay
    k_dt_scan<<<N_CHNK * N_H, C_S>>>(xbcdt, dt_bias, A_log, Acum, dtv);
    // 3) chunk end-states
    k_states<<<N_CHNK * N_H, 256, SMEM_STATES>>>(xbcdt, Acum, dtv, statesp);
    // 4) CB = C @ B^T per chunk
    {
        dim3 g(N_CHNK, 4);
        k_cb<<<g, 256, SMEM_CB>>>(xbcdt, CBp);
    }
    // 5) inter-chunk recurrence
    k_chunkscan<<<N_B * N_H, 256>>>(statesp, Acum, prevp);
    // 6) Y = diag + off + skip  (writes split bf16 y)
    k_y<<<N_CHNK * N_H, 256, SMEM_Y>>>(xbcdt, Acum, dtv, CBp, prevp, Dp);
    // 7) out-projection GEMM (HMMA): out = y @ W_out^T  (8192 x 1024 x 1024)
    {
        dim3 g(D_M / 128, M_TOT / 128);              // 8 x 64
        gemm_tc<false><<<g, 256, GEMM_SMEM>>>(yhi, ylo, w2hi, w2lo, out, D_M);
    }
    (void)in_sizes; (void)n_in; (void)out_size;
}

// round 8
// speedup vs baseline: 2.0651x; 1.2045x over previous
#include <cuda_runtime.h>
#include <cuda_bf16.h>
#include <math.h>
#include <cstdint>

// ---------------- problem constants ----------------
constexpr int D_M    = 1024;
constexpr int D_S    = 64;
constexpr int H_D    = 32;
constexpr int N_H    = 32;
constexpr int C_S    = 256;
constexpr int N_B    = 2;
constexpr int L_L    = 4096;
constexpr int N_C    = L_L / C_S;            // 16 chunks per batch
constexpr int D_PROJ = D_M + 2 * D_S + N_H;  // 1184
constexpr int M_TOT  = N_B * L_L;            // 8192
constexpr int N_CHNK = N_B * N_C;            // 32 total chunks

// ---------------- scratch (static device globals; no runtime alloc) ----------------
__device__ float g_xbcdt [M_TOT * D_PROJ];                  // 38.8 MB
__device__ float g_Acum  [N_CHNK * N_H * C_S];
__device__ float g_dtv   [N_CHNK * N_H * C_S];
__device__ float g_CB    [(size_t)N_CHNK * C_S * C_S];      // 8.4 MB
__device__ float g_states[(size_t)N_CHNK * N_H * H_D * D_S];
__device__ float g_prev  [(size_t)N_CHNK * N_H * H_D * D_S];
__device__ __nv_bfloat16 g_uhi [M_TOT * D_M];               // 16.8 MB
__device__ __nv_bfloat16 g_ulo [M_TOT * D_M];
__device__ __nv_bfloat16 g_w1hi[D_PROJ * D_M];
__device__ __nv_bfloat16 g_w1lo[D_PROJ * D_M];
__device__ __nv_bfloat16 g_w2hi[D_M * D_M];
__device__ __nv_bfloat16 g_w2lo[D_M * D_M];
__device__ __nv_bfloat16 g_yhi [M_TOT * D_M];               // 16.8 MB
__device__ __nv_bfloat16 g_ylo [M_TOT * D_M];

// ================= portable (compute_103) asm helpers =================
__device__ __forceinline__ uint32_t smem_u32(const void* p) {
    uint32_t a;
    asm("{ .reg .u64 t; cvta.to.shared.u64 t, %1; cvt.u32.u64 %0, t; }" : "=r"(a) : "l"(p));
    return a;
}
__device__ __forceinline__ void cp_async16(uint32_t dst, const void* src, int srcsize) {
    asm volatile("cp.async.cg.shared.global [%0], [%1], 16, %2;"
                 :: "r"(dst), "l"(src), "r"(srcsize) : "memory");
}
__device__ __forceinline__ void cp_commit() { asm volatile("cp.async.commit_group;" ::: "memory"); }
template<int N>
__device__ __forceinline__ void cp_wait() { asm volatile("cp.async.wait_group %0;" :: "n"(N) : "memory"); }

__device__ __forceinline__ void ldsm4(uint32_t* r, uint32_t addr) {
    asm volatile("ldmatrix.sync.aligned.m8n8.x4.shared.b16 {%0,%1,%2,%3}, [%4];"
                 : "=r"(r[0]), "=r"(r[1]), "=r"(r[2]), "=r"(r[3]) : "r"(addr));
}
__device__ __forceinline__ void mma16816(float* c, const uint32_t* a, const uint32_t* b) {
    asm volatile(
        "mma.sync.aligned.m16n8k16.row.col.f32.bf16.bf16.f32 "
        "{%0,%1,%2,%3}, {%4,%5,%6,%7}, {%8,%9}, {%0,%1,%2,%3};"
        : "+f"(c[0]), "+f"(c[1]), "+f"(c[2]), "+f"(c[3])
        : "r"(a[0]), "r"(a[1]), "r"(a[2]), "r"(a[3]), "r"(b[0]), "r"(b[1]));
}

#define SWZ128(off) ((off) ^ (((off) >> 3) & 0x70))

// ---------------- fast exp for x <= 0 (FMA pipe) ----------------
__device__ __forceinline__ float fexp(float x) {
    x = fmaxf(x, -80.0f);
    float y = x * 1.4426950408889634f;
    float z = y + 12582912.0f;
    float n = z - 12582912.0f;
    float f = y - n;
    int   ei = __float_as_int(z) - 0x4B400000;
    float s  = __int_as_float((ei + 127) << 23);
    float t = f * 0.6931471805599453f;
    float p = 1.0f + t*(1.0f + t*(0.5f + t*(0.16666667f + t*(0.041666668f + t*0.008333334f))));
    return p * s;
}

__device__ __forceinline__ uint32_t bf16pack(__nv_bfloat16 a, __nv_bfloat16 b) {
    return (uint32_t)__bfloat16_as_ushort(a) | ((uint32_t)__bfloat16_as_ushort(b) << 16);
}
// split one fp32 into (hi,lo) packed as needed
__device__ __forceinline__ void split1(float v, __nv_bfloat16& h, __nv_bfloat16& l) {
    h = __float2bfloat16(v);
    l = __float2bfloat16(v - __bfloat162float(h));
}

// ---------------- fp32 -> (hi,lo) bf16 split ----------------
__global__ void k_split(const float* __restrict__ in, __nv_bfloat16* __restrict__ hi,
                        __nv_bfloat16* __restrict__ lo, int n)
{
    for (int idx = (blockIdx.x * blockDim.x + threadIdx.x) * 4; idx < n;
         idx += gridDim.x * blockDim.x * 4) {
        float4 v = *(const float4*)(in + idx);
        __nv_bfloat16 h0, h1, h2, h3, l0, l1, l2, l3;
        split1(v.x, h0, l0); split1(v.y, h1, l1);
        split1(v.z, h2, l2); split1(v.w, h3, l3);
        *(uint2*)(hi + idx) = make_uint2(bf16pack(h0, h1), bf16pack(h2, h3));
        *(uint2*)(lo + idx) = make_uint2(bf16pack(l0, l1), bf16pack(l2, l3));
    }
}

// ================= big tensor-core GEMM (unchanged, proven) =================
constexpr int GEMM_SMEM = 2 * 4 * 16384;   // 128KB

template<bool GUARDN>
__global__ void __launch_bounds__(256)
gemm_tc(const __nv_bfloat16* __restrict__ Ahi, const __nv_bfloat16* __restrict__ Alo,
        const __nv_bfloat16* __restrict__ Bhi, const __nv_bfloat16* __restrict__ Blo,
        float* __restrict__ C, int Nrows)
{
    extern __shared__ char smem[];
    const uint32_t sb = smem_u32(smem);
    const int tid  = threadIdx.x;
    const int lane = tid & 31;
    const int wid  = tid >> 5;
    const int m0   = blockIdx.y * 128;
    const int n0   = blockIdx.x * 128;
    const int wm   = wid & 3;
    const int wn   = wid >> 2;
    constexpr int K = 1024;
    constexpr int NSTAGE = 16;

#define LOAD_STAGE(kt, buf)                                                     \
    do {                                                                        \
        const int _k0 = (kt) * 64;                                              \
        const int _bb = (buf) * 65536;                                          \
        _Pragma("unroll")                                                       \
        for (int _i = 0; _i < 16; ++_i) {                                       \
            const int _op  = _i >> 2;                                           \
            const int _c   = ((_i * 256 + tid) & 1023);                         \
            const int _row = _c >> 3, _g = _c & 7;                              \
            const uint32_t _dst = sb + _bb + _op * 16384                        \
                                + SWZ128(_row * 128 + _g * 16);                 \
            if (_op < 2) {                                                      \
                const __nv_bfloat16* _p = (_op == 0 ? Ahi : Alo)                \
                    + (size_t)(m0 + _row) * K + _k0 + _g * 8;                   \
                cp_async16(_dst, _p, 16);                                       \
            } else {                                                            \
                const int _nr = n0 + _row;                                      \
                const bool _ok = (!GUARDN || _nr < Nrows);                      \
                const __nv_bfloat16* _p = (_op == 2 ? Bhi : Blo)                \
                    + (size_t)(_ok ? _nr : 0) * K + _k0 + _g * 8;               \
                cp_async16(_dst, _p, _ok ? 16 : 0);                             \
            }                                                                   \
        }                                                                       \
        cp_commit();                                                            \
    } while (0)

    float acc[2][8][4];
#pragma unroll
    for (int mt = 0; mt < 2; ++mt)
#pragma unroll
        for (int nt = 0; nt < 8; ++nt)
#pragma unroll
            for (int q = 0; q < 4; ++q) acc[mt][nt][q] = 0.f;

    const int sub = lane >> 3;
    const int lr  = lane & 7;
    const int a_r = (sub & 1) * 8 + lr;
    const int a_c = (sub >> 1) * 16;
    const int b_r = (sub >> 1) * 8 + lr;
    const int b_c = (sub & 1) * 16;

    LOAD_STAGE(0, 0);

    for (int kt = 0; kt < NSTAGE; ++kt) {
        const int buf = kt & 1;
        if (kt + 1 < NSTAGE) { LOAD_STAGE(kt + 1, buf ^ 1); cp_wait<1>(); }
        else                 { cp_wait<0>(); }
        __syncthreads();

        const uint32_t tAh = sb + buf * 65536;
        const uint32_t tAl = tAh + 16384;
        const uint32_t tBh = tAh + 32768;
        const uint32_t tBl = tAh + 49152;
#pragma unroll
        for (int ks = 0; ks < 4; ++ks) {
            uint32_t ah[2][4], al[2][4], bh[16], bl[16];
#pragma unroll
            for (int mt = 0; mt < 2; ++mt) {
                const int off = (wm * 32 + mt * 16 + a_r) * 128 + ks * 32 + a_c;
                const uint32_t so = SWZ128(off);
                ldsm4(ah[mt], tAh + so);
                ldsm4(al[mt], tAl + so);
            }
#pragma unroll
            for (int pr = 0; pr < 4; ++pr) {
                const int off = (wn * 64 + pr * 16 + b_r) * 128 + ks * 32 + b_c;
                const uint32_t so = SWZ128(off);
                ldsm4(&bh[pr * 4], tBh + so);
                ldsm4(&bl[pr * 4], tBl + so);
            }
#pragma unroll
            for (int mt = 0; mt < 2; ++mt)
#pragma unroll
                for (int nt = 0; nt < 8; ++nt) {
                    mma16816(acc[mt][nt], ah[mt], &bh[nt * 2]);
                    mma16816(acc[mt][nt], ah[mt], &bl[nt * 2]);
                    mma16816(acc[mt][nt], al[mt], &bh[nt * 2]);
                }
        }
        __syncthreads();
    }
#undef LOAD_STAGE

    const int rbase = m0 + wm * 32 + (lane >> 2);
    const int cq    = (lane & 3) * 2;
#pragma unroll
    for (int mt = 0; mt < 2; ++mt) {
#pragma unroll
        for (int nt = 0; nt < 8; ++nt) {
            const int col = n0 + wn * 64 + nt * 8 + cq;
            if (!GUARDN || col < Nrows) {
                float* p = C + (size_t)(rbase + mt * 16) * Nrows + col;
                p[0] = acc[mt][nt][0];
                p[1] = acc[mt][nt][1];
                float* q = p + 8 * (size_t)Nrows;
                q[0] = acc[mt][nt][2];
                q[1] = acc[mt][nt][3];
            }
        }
    }
}

// ---------------- dt = softplus(raw + bias), a = dt*A, per-chunk inclusive cumsum --
__global__ void k_dt_scan(const float* __restrict__ xbcdt,
                          const float* __restrict__ dt_bias,
                          const float* __restrict__ A_log,
                          float* __restrict__ Acum, float* __restrict__ dtv)
{
    const int blk = blockIdx.x;
    const int h   = blk & (N_H - 1);
    const int bc  = blk >> 5;
    const int i   = threadIdx.x;
    const size_t m = (size_t)bc * C_S + i;

    float z  = xbcdt[m * D_PROJ + (D_M + 2 * D_S) + h] + dt_bias[h];
    float dt = (z > 20.f) ? z : log1pf(__expf(z));
    float a  = dt * (-__expf(A_log[h]));

    __shared__ float ss[C_S];
    ss[i] = a;
    __syncthreads();
#pragma unroll
    for (int off = 1; off < C_S; off <<= 1) {
        float v = (i >= off) ? ss[i - off] : 0.f;
        __syncthreads();
        ss[i] += v;
        __syncthreads();
    }
    Acum[(size_t)blk * C_S + i] = ss[i];
    dtv [(size_t)blk * C_S + i] = dt;
}

// ---------------- per-(b,c,h) chunk states (unchanged SIMT) ----------------------
__global__ void __launch_bounds__(256)
k_states(const float* __restrict__ xbcdt,
         const float* __restrict__ Acum, const float* __restrict__ dtv,
         float* __restrict__ states)
{
    extern __shared__ float sm[];
    float* sB = sm;                // [256][65]
    float* sx = sm + C_S * 65;     // [256][32]

    const int blk  = blockIdx.x;
    const int h    = blk & 31;
    const int bc   = blk >> 5;
    const int tid  = threadIdx.x;
    const int lane = tid & 31;
    const int warp = tid >> 5;
    const size_t m0 = (size_t)bc * C_S;
    const float* AcR = Acum + (size_t)blk * C_S;
    const float* dtR = dtv  + (size_t)blk * C_S;
    const float Alast = AcR[C_S - 1];

    for (int j = warp; j < C_S; j += 8) {
        const float* row = xbcdt + (m0 + j) * D_PROJ;
        float w = fexp(Alast - AcR[j]) * dtR[j];
        sB[j * 65 + lane]      = row[D_M + lane];
        sB[j * 65 + lane + 32] = row[D_M + lane + 32];
        sx[j * 32 + lane]      = row[h * H_D + lane] * w;
    }
    __syncthreads();

    const int p  = tid >> 3;
    const int n0 = (tid & 7) << 3;
    float acc[8];
#pragma unroll
    for (int q = 0; q < 8; ++q) acc[q] = 0.f;
    for (int j = 0; j < C_S; ++j) {
        float xv = sx[j * 32 + p];
        const float* bp = &sB[j * 65 + n0];
#pragma unroll
        for (int q = 0; q < 8; ++q) acc[q] += xv * bp[q];
    }
    float* out = states + (size_t)blk * (H_D * D_S) + p * D_S + n0;
#pragma unroll
    for (int q = 0; q < 8; ++q) out[q] = acc[q];
}

// ================= k_cb_tc: CB = C @ B^T per chunk via HMMA ======================
// grid (32, 3): y=0 -> (ti,tj)=(0,0), 1 -> (1,0), 2 -> (1,1). Tile (0,1) masked.
// smem: AHI 0, ALO 16K, BHI 32K, BLO 48K (each 128 rows x 64 bf16, SW128)
__global__ void __launch_bounds__(256)
k_cb_tc(const float* __restrict__ xbcdt, float* __restrict__ CB)
{
    extern __shared__ char smem[];
    const uint32_t sb = smem_u32(smem);
    const int tid  = threadIdx.x;
    const int lane = tid & 31;
    const int wid  = tid >> 5;
    const int bc   = blockIdx.x;
    const int ty   = blockIdx.y;
    const int ti   = (ty + 1) >> 1;
    const int tj   = ty >> 1;
    const size_t m0 = (size_t)bc * C_S;

    // stage C (A-op) and B (B-op): 128 rows x 16 float4 each
    for (int e = tid; e < 4096; e += 256) {
        const int op = e >> 11;                 // 0 = C, 1 = B
        const int r  = (e >> 4) & 127;
        const int c4 = e & 15;
        const size_t grow = m0 + (op ? tj : ti) * 128 + r;
        const int colb = D_M + (op ? 0 : D_S) + c4 * 4;
        float4 v = *(const float4*)(xbcdt + grow * D_PROJ + colb);
        __nv_bfloat16 h0, h1, h2, h3, l0, l1, l2, l3;
        split1(v.x, h0, l0); split1(v.y, h1, l1);
        split1(v.z, h2, l2); split1(v.w, h3, l3);
        const uint32_t so = SWZ128(r * 128 + c4 * 8);
        const int hbase = op ? 32768 : 0;
        *(uint2*)(smem + hbase + so)         = make_uint2(bf16pack(h0, h1), bf16pack(h2, h3));
        *(uint2*)(smem + hbase + 16384 + so) = make_uint2(bf16pack(l0, l1), bf16pack(l2, l3));
    }
    __syncthreads();

    const int wm = wid & 3, wn = wid >> 2;
    const int sub = lane >> 3, lr = lane & 7;
    const int a_r = (sub & 1) * 8 + lr, a_c = (sub >> 1) * 16;
    const int b_r = (sub >> 1) * 8 + lr, b_c = (sub & 1) * 16;

    float acc[2][8][4];
#pragma unroll
    for (int mt = 0; mt < 2; ++mt)
#pragma unroll
        for (int nt = 0; nt < 8; ++nt)
#pragma unroll
            for (int q = 0; q < 4; ++q) acc[mt][nt][q] = 0.f;

#pragma unroll
    for (int ks = 0; ks < 4; ++ks) {
        uint32_t ah[2][4], al[2][4], bh[16], bl[16];
#pragma unroll
        for (int mt = 0; mt < 2; ++mt) {
            const uint32_t so = SWZ128((wm * 32 + mt * 16 + a_r) * 128 + ks * 32 + a_c);
            ldsm4(ah[mt], sb + so);
            ldsm4(al[mt], sb + 16384 + so);
        }
#pragma unroll
        for (int pr = 0; pr < 4; ++pr) {
            const uint32_t so = SWZ128((wn * 64 + pr * 16 + b_r) * 128 + ks * 32 + b_c);
            ldsm4(&bh[pr * 4], sb + 32768 + so);
            ldsm4(&bl[pr * 4], sb + 49152 + so);
        }
#pragma unroll
        for (int mt = 0; mt < 2; ++mt)
#pragma unroll
            for (int nt = 0; nt < 8; ++nt) {
                mma16816(acc[mt][nt], ah[mt], &bh[nt * 2]);
                mma16816(acc[mt][nt], ah[mt], &bl[nt * 2]);
                mma16816(acc[mt][nt], al[mt], &bh[nt * 2]);
            }
    }

    float* cbB = CB + (size_t)bc * (C_S * C_S);
    const int rb = ti * 128 + wm * 32 + (lane >> 2);
    const int cq = (lane & 3) * 2;
#pragma unroll
    for (int mt = 0; mt < 2; ++mt)
#pragma unroll
        for (int nt = 0; nt < 8; ++nt) {
            const int col = tj * 128 + wn * 64 + nt * 8 + cq;
            float* p = cbB + (size_t)(rb + mt * 16) * C_S + col;
            p[0] = acc[mt][nt][0]; p[1] = acc[mt][nt][1];
            float* q = p + 8 * C_S;
            q[0] = acc[mt][nt][2]; q[1] = acc[mt][nt][3];
        }
}

// ---------------- inter-chunk recurrence (unchanged) -----------------------------
__global__ void k_chunkscan(const float* __restrict__ states,
                            const float* __restrict__ Acum,
                            float* __restrict__ prev)
{
    const int blk = blockIdx.x;
    const int h   = blk & 31;
    const int b   = blk >> 5;
    const int e   = threadIdx.x * 8;
    float s[8];
#pragma unroll
    for (int q = 0; q < 8; ++q) s[q] = 0.f;
    for (int c = 0; c < N_C; ++c) {
        const int bc = b * N_C + c;
        const size_t base = ((size_t)bc * N_H + h) * (H_D * D_S) + e;
#pragma unroll
        for (int q = 0; q < 8; ++q) prev[base + q] = s[q];
        float dec = __expf(Acum[((size_t)bc * N_H + h) * C_S + (C_S - 1)]);
#pragma unroll
        for (int q = 0; q < 8; ++q) s[q] = s[q] * dec + states[base + q];
    }
}

// ================= k_y_tc: Y = (CB.L)@xdt + (C e^A)@prev^T + D*x via HMMA =======
// smem layout (bytes):
//   sAc   @ 0       : 256 f32
//   XHI   @ 1024    : 4 tiles x [32 p][64 j] bf16 (4KB each)
//   XLO   @ 17408
//   SHI   @ 33792   : [256 i][64 j] bf16 (32KB)   (reused for Ce)
//   SLO   @ 66560
//   PHI   @ 99328   : [32 p][64 n] bf16 (4KB)
//   PLO   @ 103424  ; total 107520
constexpr int YT_AC  = 0;
constexpr int YT_XHI = 1024;
constexpr int YT_XLO = 17408;
constexpr int YT_SHI = 33792;
constexpr int YT_SLO = 66560;
constexpr int YT_PHI = 99328;
constexpr int YT_PLO = 103424;
constexpr int YT_SMEM = 107520;

__global__ void __launch_bounds__(256, 2)
k_y_tc(const float* __restrict__ xbcdt,
       const float* __restrict__ Acum, const float* __restrict__ dtv,
       const float* __restrict__ CB, const float* __restrict__ prev,
       const float* __restrict__ Dp)
{
    extern __shared__ __align__(128) char smem[];
    const uint32_t sb = smem_u32(smem);
    float* sAc = (float*)smem;

    const int blk  = blockIdx.x;   // bc*32 + h
    const int h    = blk & 31;
    const int bc   = blk >> 5;
    const int tid  = threadIdx.x;
    const int lane = tid & 31;
    const int wid  = tid >> 5;     // 0..7; warp owns output rows [wid*32, wid*32+32)
    const size_t m0 = (size_t)bc * C_S;

    sAc[tid] = Acum[(size_t)blk * C_S + tid];

    // ---- stage xdt transposed: sxdtT[tile][p][j]  (bf16 hi/lo, SW128 within tile)
    {
        const int j = tid;
        const float dt = dtv[(size_t)blk * C_S + j];
        const float* xr = xbcdt + (m0 + j) * D_PROJ + h * H_D;
        const int tile = j >> 6, jl = j & 63;
        char* hib = smem + YT_XHI + tile * 4096;
        char* lob = smem + YT_XLO + tile * 4096;
#pragma unroll
        for (int p4 = 0; p4 < 8; ++p4) {
            float4 v = ((const float4*)xr)[p4];
            v.x *= dt; v.y *= dt; v.z *= dt; v.w *= dt;
            const float vv[4] = {v.x, v.y, v.z, v.w};
#pragma unroll
            for (int e = 0; e < 4; ++e) {
                __nv_bfloat16 hv, lv;
                split1(vv[e], hv, lv);
                const uint32_t so = SWZ128((p4 * 4 + e) * 128 + jl * 2);
                *(__nv_bfloat16*)(hib + so) = hv;
                *(__nv_bfloat16*)(lob + so) = lv;
            }
        }
    }
    // ---- stage prev^T operand: [p][n] n-contig (canonical B layout already)
    {
        const int p  = tid >> 3;
        const int n0 = (tid & 7) * 8;
        const float* pv = prev + (size_t)blk * (H_D * D_S) + p * D_S + n0;
        float4 a = ((const float4*)pv)[0];
        float4 b = ((const float4*)pv)[1];
        __nv_bfloat16 h0,h1,h2,h3,h4,h5,h6,h7, l0,l1,l2,l3,l4,l5,l6,l7;
        split1(a.x,h0,l0); split1(a.y,h1,l1); split1(a.z,h2,l2); split1(a.w,h3,l3);
        split1(b.x,h4,l4); split1(b.y,h5,l5); split1(b.z,h6,l6); split1(b.w,h7,l7);
        const uint32_t so = SWZ128(p * 128 + n0 * 2);
        *(uint4*)(smem + YT_PHI + so) = make_uint4(bf16pack(h0,h1), bf16pack(h2,h3),
                                                  bf16pack(h4,h5), bf16pack(h6,h7));
        *(uint4*)(smem + YT_PLO + so) = make_uint4(bf16pack(l0,l1), bf16pack(l2,l3),
                                                  bf16pack(l4,l5), bf16pack(l6,l7));
    }

    float acc[2][4][4];
#pragma unroll
    for (int mt = 0; mt < 2; ++mt)
#pragma unroll
        for (int nt = 0; nt < 4; ++nt)
#pragma unroll
            for (int q = 0; q < 4; ++q) acc[mt][nt][q] = 0.f;

    const int sub = lane >> 3, lr = lane & 7;
    const int a_r = (sub & 1) * 8 + lr, a_c = (sub >> 1) * 16;
    const int b_r = (sub >> 1) * 8 + lr, b_c = (sub & 1) * 16;
    const float* cbB = CB + (size_t)bc * (C_S * C_S);

    // ================= diagonal part: 4 j-tiles of 64 =================
    for (int t = 0; t < 4; ++t) {
        const int j0 = t * 64;
        const bool active = (wid * 32 + 31) >= j0;
        __syncthreads();
        if (active) {
            // build S rows owned by this warp: lanes cover 2 j-cols each
            const int jj = lane * 2;
            const float Aj0 = sAc[j0 + jj];
            const float Aj1 = sAc[j0 + jj + 1];
#pragma unroll 4
            for (int r = 0; r < 32; ++r) {
                const int i = wid * 32 + r;
                uint32_t hv = 0, lv = 0;
                if (i >= j0) {
                    const float2 cb = *(const float2*)(cbB + (size_t)i * C_S + j0 + jj);
                    const float Ai = sAc[i];
                    const float s0 = (j0 + jj     <= i) ? cb.x * fexp(Ai - Aj0) : 0.f;
                    const float s1 = (j0 + jj + 1 <= i) ? cb.y * fexp(Ai - Aj1) : 0.f;
                    __nv_bfloat16 hb0, lb0, hb1, lb1;
                    split1(s0, hb0, lb0); split1(s1, hb1, lb1);
                    hv = bf16pack(hb0, hb1); lv = bf16pack(lb0, lb1);
                }
                const uint32_t so = SWZ128(i * 128 + jj * 2);
                *(uint32_t*)(smem + YT_SHI + so) = hv;
                *(uint32_t*)(smem + YT_SLO + so) = lv;
            }
        }
        __syncthreads();
        if (active) {
            const uint32_t xh = sb + YT_XHI + t * 4096;
            const uint32_t xl = sb + YT_XLO + t * 4096;
#pragma unroll
            for (int ks = 0; ks < 4; ++ks) {
                uint32_t ah[2][4], al[2][4], bh[8], bl[8];
#pragma unroll
                for (int mt = 0; mt < 2; ++mt) {
                    const uint32_t so = SWZ128((wid * 32 + mt * 16 + a_r) * 128 + ks * 32 + a_c);
                    ldsm4(ah[mt], sb + YT_SHI + so);
                    ldsm4(al[mt], sb + YT_SLO + so);
                }
#pragma unroll
                for (int pr = 0; pr < 2; ++pr) {
                    const uint32_t so = SWZ128((pr * 16 + b_r) * 128 + ks * 32 + b_c);
                    ldsm4(&bh[pr * 4], xh + so);
                    ldsm4(&bl[pr * 4], xl + so);
                }
#pragma unroll
                for (int mt = 0; mt < 2; ++mt)
#pragma unroll
                    for (int nt = 0; nt < 4; ++nt) {
                        mma16816(acc[mt][nt], ah[mt], &bh[nt * 2]);
                        mma16816(acc[mt][nt], ah[mt], &bl[nt * 2]);
                        mma16816(acc[mt][nt], al[mt], &bh[nt * 2]);
                    }
            }
        }
    }

    // ================= off part: Ce = C * exp(Acum) into S buffer, K = 64 ========
    __syncthreads();
    {
        const int nn = lane * 2;
#pragma unroll 4
        for (int r = 0; r < 32; ++r) {
            const int i = wid * 32 + r;
            const float eA = fexp(sAc[i]);
            const float2 cv = *(const float2*)(xbcdt + (m0 + i) * D_PROJ + D_M + D_S + nn);
            __nv_bfloat16 hb0, lb0, hb1, lb1;
            split1(cv.x * eA, hb0, lb0); split1(cv.y * eA, hb1, lb1);
            const uint32_t so = SWZ128(i * 128 + nn * 2);
            *(uint32_t*)(smem + YT_SHI + so) = bf16pack(hb0, hb1);
            *(uint32_t*)(smem + YT_SLO + so) = bf16pack(lb0, lb1);
        }
    }
    __syncthreads();
    {
#pragma unroll
        for (int ks = 0; ks < 4; ++ks) {
            uint32_t ah[2][4], al[2][4], bh[8], bl[8];
#pragma unroll
            for (int mt = 0; mt < 2; ++mt) {
                const uint32_t so = SWZ128((wid * 32 + mt * 16 + a_r) * 128 + ks * 32 + a_c);
                ldsm4(ah[mt], sb + YT_SHI + so);
                ldsm4(al[mt], sb + YT_SLO + so);
            }
#pragma unroll
            for (int pr = 0; pr < 2; ++pr) {
                const uint32_t so = SWZ128((pr * 16 + b_r) * 128 + ks * 32 + b_c);
                ldsm4(&bh[pr * 4], sb + YT_PHI + so);
                ldsm4(&bl[pr * 4], sb + YT_PLO + so);
            }
#pragma unroll
            for (int mt = 0; mt < 2; ++mt)
#pragma unroll
                for (int nt = 0; nt < 4; ++nt) {
                    mma16816(acc[mt][nt], ah[mt], &bh[nt * 2]);
                    mma16816(acc[mt][nt], ah[mt], &bl[nt * 2]);
                    mma16816(acc[mt][nt], al[mt], &bh[nt * 2]);
                }
        }
    }

    // ================= epilogue: + D*x (fp32-exact), split-bf16 store ============
    const float Dh = Dp[h];
    const int rl = wid * 32 + (lane >> 2);
    const int cq = (lane & 3) * 2;
#pragma unroll
    for (int mt = 0; mt < 2; ++mt) {
#pragma unroll
        for (int nt = 0; nt < 4; ++nt) {
            const int p = nt * 8 + cq;
#pragma unroll
            for (int half = 0; half < 2; ++half) {
                const int row = rl + mt * 16 + half * 8;
                const size_t gi = m0 + row;
                const float2 xv = *(const float2*)(xbcdt + gi * D_PROJ + h * H_D + p);
                const float y0 = acc[mt][nt][half * 2]     + Dh * xv.x;
                const float y1 = acc[mt][nt][half * 2 + 1] + Dh * xv.y;
                __nv_bfloat16 hb0, lb0, hb1, lb1;
                split1(y0, hb0, lb0); split1(y1, hb1, lb1);
                const size_t yo = gi * D_M + h * H_D + p;
                *(uint32_t*)(g_yhi + yo) = bf16pack(hb0, hb1);
                *(uint32_t*)(g_ylo + yo) = bf16pack(lb0, lb1);
            }
        }
    }
}

// ---------------- launch ----------------
extern "C" void kernel_launch(void* const* d_in, const int* in_sizes, int n_in,
                              void* d_out, int out_size)
{
    const float* u       = (const float*)d_in[0];
    const float* W_in    = (const float*)d_in[1];
    const float* dt_bias = (const float*)d_in[2];
    const float* A_log   = (const float*)d_in[3];
    const float* Dp      = (const float*)d_in[4];
    const float* W_out   = (const float*)d_in[5];
    float* out = (float*)d_out;

    float *xbcdt, *Acum, *dtv, *CBp, *statesp, *prevp;
    __nv_bfloat16 *uhi, *ulo, *w1hi, *w1lo, *w2hi, *w2lo, *yhi, *ylo;
    cudaGetSymbolAddress((void**)&xbcdt,  g_xbcdt);
    cudaGetSymbolAddress((void**)&Acum,   g_Acum);
    cudaGetSymbolAddress((void**)&dtv,    g_dtv);
    cudaGetSymbolAddress((void**)&CBp,    g_CB);
    cudaGetSymbolAddress((void**)&statesp,g_states);
    cudaGetSymbolAddress((void**)&prevp,  g_prev);
    cudaGetSymbolAddress((void**)&uhi,    g_uhi);
    cudaGetSymbolAddress((void**)&ulo,    g_ulo);
    cudaGetSymbolAddress((void**)&w1hi,   g_w1hi);
    cudaGetSymbolAddress((void**)&w1lo,   g_w1lo);
    cudaGetSymbolAddress((void**)&w2hi,   g_w2hi);
    cudaGetSymbolAddress((void**)&w2lo,   g_w2lo);
    cudaGetSymbolAddress((void**)&yhi,    g_yhi);
    cudaGetSymbolAddress((void**)&ylo,    g_ylo);

    const int SMEM_STATES = (C_S * 65 + C_S * 32) * 4;
    cudaFuncSetAttribute(k_states, cudaFuncAttributeMaxDynamicSharedMemorySize, SMEM_STATES);
    cudaFuncSetAttribute(k_cb_tc,  cudaFuncAttributeMaxDynamicSharedMemorySize, 65536);
    cudaFuncSetAttribute(k_y_tc,   cudaFuncAttributeMaxDynamicSharedMemorySize, YT_SMEM);
    cudaFuncSetAttribute(gemm_tc<true>,  cudaFuncAttributeMaxDynamicSharedMemorySize, GEMM_SMEM);
    cudaFuncSetAttribute(gemm_tc<false>, cudaFuncAttributeMaxDynamicSharedMemorySize, GEMM_SMEM);

    // 0) split fp32 inputs into (hi,lo) bf16 pairs
    k_split<<<512, 256>>>(u,     uhi,  ulo,  M_TOT * D_M);
    k_split<<<96,  256>>>(W_in,  w1hi, w1lo, D_PROJ * D_M);
    k_split<<<96,  256>>>(W_out, w2hi, w2lo, D_M * D_M);

    // 1) in-projection GEMM (HMMA): xbcdt = u @ W_in^T
    {
        dim3 g((D_PROJ + 127) / 128, M_TOT / 128);
        gemm_tc<true><<<g, 256, GEMM_SMEM>>>(uhi, ulo, w1hi, w1lo, xbcdt, D_PROJ);
    }
    // 2) dt + per-chunk cumulative decay
    k_dt_scan<<<N_CHNK * N_H, C_S>>>(xbcdt, dt_bias, A_log, Acum, dtv);
    // 3) chunk end-states
    k_states<<<N_CHNK * N_H, 256, SMEM_STATES>>>(xbcdt, Acum, dtv, statesp);
    // 4) CB = C @ B^T per chunk (HMMA, causal tiles only)
    {
        dim3 g(N_CHNK, 3);
        k_cb_tc<<<g, 256, 65536>>>(xbcdt, CBp);
    }
    // 5) inter-chunk recurrence
    k_chunkscan<<<N_B * N_H, 256>>>(statesp, Acum, prevp);
    // 6) Y (HMMA) -> split bf16 y
    k_y_tc<<<N_CHNK * N_H, 256, YT_SMEM>>>(xbcdt, Acum, dtv, CBp, prevp, Dp);
    // 7) out-projection GEMM (HMMA): out = y @ W_out^T
    {
        dim3 g(D_M / 128, M_TOT / 128);
        gemm_tc<false><<<g, 256, GEMM_SMEM>>>(yhi, ylo, w2hi, w2lo, out, D_M);
    }
    (void)in_sizes; (void)n_in; (void)out_size;
}